// round 14
// baseline (speedup 1.0000x reference)
#include <cuda_runtime.h>
#include <cuda_bf16.h>
#include <math.h>
#include <stdint.h>

#define N_NODES 100000
#define E_MAX   1750000
#define SCAN_B  1024
#define SCAN_NB ((N_NODES + SCAN_B - 1) / SCAN_B)   // 98

// ---------------- scratch (device globals; no allocation allowed) ----------
__device__ __nv_bfloat16 g_hb[N_NODES * 64];   // bf16 features (GEMM out / aggr in)
__device__ float g_buf1[N_NODES * 64];
__device__ float g_buf2[N_NODES * 64];
__device__ float g_as  [N_NODES];
__device__ float g_ad  [N_NODES];
__device__ int   g_deg [N_NODES];
__device__ int   g_off [N_NODES + 1];
__device__ int   g_cur [N_NODES];
__device__ int   g_csr [E_MAX];
__device__ int   g_bsum[128];
__device__ int   g_is32;

// ---------------- dtype detection (parallel) --------------------------------
__global__ void detect_kernel(const int* __restrict__ ei32, int nWords) {
    int lim = nWords < 65536 ? nWords : 65536;
    int any = 0;
    for (int i = 1 + 2 * threadIdx.x; i < lim; i += 2 * blockDim.x)
        any |= (ei32[i] != 0);
    any = __syncthreads_or(any);
    if (threadIdx.x == 0) g_is32 = any ? 1 : 0;
}

__device__ __forceinline__ int load_idx(const int* ei32, const long long* ei64,
                                        int is32, int i) {
    return is32 ? ei32[i] : (int)ei64[i];
}

// ---------------- CSR build --------------------------------------------------
__global__ void zero_int_kernel(int* p, int n) {
    int i = blockIdx.x * blockDim.x + threadIdx.x;
    if (i < n) p[i] = 0;
}

__global__ void hist_kernel(const void* __restrict__ ei, int* __restrict__ deg,
                            int nE, int nN) {
    int i = blockIdx.x * blockDim.x + threadIdx.x;
    int nTot = nE + nN;
    if (i >= nTot) return;
    int is32 = g_is32;
    const int* e32 = (const int*)ei;
    const long long* e64 = (const long long*)ei;
    int d = (i < nE) ? load_idx(e32, e64, is32, nE + i) : (i - nE);
    atomicAdd(&deg[d], 1);
}

__global__ void scanA_kernel(const int* __restrict__ deg, int* __restrict__ off,
                             int* __restrict__ bsum, int n) {
    __shared__ int sm[SCAN_B];
    int tid = threadIdx.x;
    int i = blockIdx.x * SCAN_B + tid;
    int v = (i < n) ? deg[i] : 0;
    sm[tid] = v;
    __syncthreads();
    #pragma unroll
    for (int s = 1; s < SCAN_B; s <<= 1) {
        int t = (tid >= s) ? sm[tid - s] : 0;
        __syncthreads();
        sm[tid] += t;
        __syncthreads();
    }
    if (i < n) off[i] = sm[tid] - v;
    if (tid == SCAN_B - 1) bsum[blockIdx.x] = sm[tid];
}

__global__ void scanB_kernel(int* __restrict__ bsum, int nb,
                             int* __restrict__ off, int n) {
    __shared__ int sm[128];
    int tid = threadIdx.x;
    int v = (tid < nb) ? bsum[tid] : 0;
    sm[tid] = v;
    __syncthreads();
    #pragma unroll
    for (int s = 1; s < 128; s <<= 1) {
        int t = (tid >= s) ? sm[tid - s] : 0;
        __syncthreads();
        sm[tid] += t;
        __syncthreads();
    }
    if (tid < nb) bsum[tid] = sm[tid] - v;
    if (tid == 127) off[n] = sm[127];
}

__global__ void scanC_kernel(int* __restrict__ off, int* __restrict__ cur,
                             const int* __restrict__ bsum, int n) {
    int i = blockIdx.x * SCAN_B + threadIdx.x;
    if (i >= n) return;
    int v = off[i] + bsum[blockIdx.x];
    off[i] = v;
    cur[i] = v;
}

__global__ void scatter_kernel(const void* __restrict__ ei,
                               int* __restrict__ cur, int* __restrict__ csr,
                               int nE, int nN) {
    int i = blockIdx.x * blockDim.x + threadIdx.x;
    int nTot = nE + nN;
    if (i >= nTot) return;
    int is32 = g_is32;
    const int* e32 = (const int*)ei;
    const long long* e64 = (const long long*)ei;
    int s, d;
    if (i < nE) {
        s = load_idx(e32, e64, is32, i);
        d = load_idx(e32, e64, is32, nE + i);
    } else {
        s = d = i - nE;
    }
    int pos = atomicAdd(&cur[d], 1);
    csr[pos] = s;
}

// ---------------- tensor-core GEMM (bf16x2-split, ldmatrix, ping-pong) ------
#define MMA_BF16(D, A0, A1, A2, A3, B0, B1)                                    \
    asm volatile(                                                              \
        "mma.sync.aligned.m16n8k16.row.col.f32.bf16.bf16.f32 "                 \
        "{%0,%1,%2,%3}, {%4,%5,%6,%7}, {%8,%9}, {%0,%1,%2,%3};\n"              \
        : "+f"(D[0]), "+f"(D[1]), "+f"(D[2]), "+f"(D[3])                       \
        : "r"(A0), "r"(A1), "r"(A2), "r"(A3), "r"(B0), "r"(B1))

#define LDSM4(R, ADDR)                                                         \
    asm volatile(                                                              \
        "ldmatrix.sync.aligned.m8n8.x4.shared.b16 {%0,%1,%2,%3}, [%4];\n"      \
        : "=r"(R[0]), "=r"(R[1]), "=r"(R[2]), "=r"(R[3]) : "r"(ADDR))

// per-stage layout (bf16 elements): Ah[128*40] Al[128*40] Bh[64*40] Bl[64*40]
#define GSTR   40
#define A_ELEM (128 * GSTR)
#define B_ELEM (64 * GSTR)
#define STAGE_BYTES ((2 * A_ELEM + 2 * B_ELEM) * 2)   // 30720
#define GEMM_DYN_SMEM (2 * STAGE_BYTES)               // 61440

template <int NT>   // NT = N/8 (8 for N=64, 4 for N=32); NT even
__global__ __launch_bounds__(256, 2) void gemm_tc_kernel(
    const float* __restrict__ A, const float* __restrict__ B,
    __nv_bfloat16* __restrict__ Hb, int M, int K, int N,
    const float* __restrict__ asrc, const float* __restrict__ adst,
    float* __restrict__ as_, float* __restrict__ ad_) {
    const int BM = 128, BK = 32, STR = GSTR;
    extern __shared__ __align__(16) char dyns[];

    int tid  = threadIdx.x;
    int warp = tid >> 5;
    int lane = tid & 31;
    int g = lane >> 2;
    int t = lane & 3;
    int bm = blockIdx.x * BM;

    uint32_t smemBase = (uint32_t)__cvta_generic_to_shared(dyns);
    // ldmatrix per-lane offsets within a stage
    int aRow = warp * 16 + (lane & 15);
    int aCol = (lane >> 4) * 8;
    uint32_t aOffH0 = smemBase + (aRow * STR + aCol) * 2;
    uint32_t aOffL0 = aOffH0 + A_ELEM * 2;
    int bRow = (lane & 7) + ((lane >> 4) << 3);
    int bCol = ((lane >> 3) & 1) * 8;
    uint32_t bOffH0 = smemBase + (2 * A_ELEM) * 2 + (bRow * STR + bCol) * 2;
    uint32_t bOffL0 = bOffH0 + B_ELEM * 2;

    float d[NT][4];
    #pragma unroll
    for (int nt = 0; nt < NT; ++nt)
        #pragma unroll
        for (int r = 0; r < 4; ++r) d[nt][r] = 0.f;

    int ntiles = K / BK;

    // ---- tile store helper (load global -> convert hi/lo -> STS) ----
    auto storeTile = [&](int ti, int st) {
        __nv_bfloat16* Ah = (__nv_bfloat16*)(dyns + st * STAGE_BYTES);
        __nv_bfloat16* Al = Ah + A_ELEM;
        __nv_bfloat16* Bh = Al + A_ELEM;
        __nv_bfloat16* Bl = Bh + B_ELEM;
        int k0 = ti * BK;
        #pragma unroll
        for (int it = 0; it < 8; ++it) {
            int idx2 = tid + it * 256;         // pair index, 2048 pairs
            int m  = idx2 >> 4;
            int kp = (idx2 & 15) * 2;
            int gm = bm + m;
            float2 v = make_float2(0.f, 0.f);
            if (gm < M) v = *(const float2*)(A + (size_t)gm * K + k0 + kp);
            __nv_bfloat16 h0 = __float2bfloat16(v.x);
            __nv_bfloat16 h1 = __float2bfloat16(v.y);
            __nv_bfloat162 ph; ph.x = h0; ph.y = h1;
            __nv_bfloat162 pl;
            pl.x = __float2bfloat16(v.x - __bfloat162float(h0));
            pl.y = __float2bfloat16(v.y - __bfloat162float(h1));
            *(__nv_bfloat162*)(Ah + m * STR + kp) = ph;
            *(__nv_bfloat162*)(Al + m * STR + kp) = pl;
        }
        #pragma unroll
        for (int it = 0; it < 8; ++it) {
            int idx = tid + it * 256;          // 2048 elements
            int k = idx >> 6, n = idx & 63;
            float v = 0.f;
            if (n < N) v = B[(size_t)(k0 + k) * N + n];
            __nv_bfloat16 h0 = __float2bfloat16(v);
            Bh[n * STR + k] = h0;
            Bl[n * STR + k] = __float2bfloat16(v - __bfloat162float(h0));
        }
    };

    // prologue: fill stage 0
    storeTile(0, 0);
    __syncthreads();

    for (int i = 0; i < ntiles; ++i) {
        int cur = i & 1;
        // store next tile into the other stage (overlaps mma across warps)
        if (i + 1 < ntiles) storeTile(i + 1, cur ^ 1);

        uint32_t stOff = (uint32_t)cur * STAGE_BYTES;
        #pragma unroll
        for (int kk = 0; kk < BK; kk += 16) {
            unsigned int ah[4], al[4];
            LDSM4(ah, aOffH0 + stOff + kk * 2);
            LDSM4(al, aOffL0 + stOff + kk * 2);
            #pragma unroll
            for (int p = 0; p < NT / 2; ++p) {
                unsigned int bh[4], bl[4];
                LDSM4(bh, bOffH0 + stOff + (p * 16 * STR + kk) * 2);
                LDSM4(bl, bOffL0 + stOff + (p * 16 * STR + kk) * 2);
                MMA_BF16(d[2 * p],     ah[0], ah[1], ah[2], ah[3], bh[0], bh[1]);
                MMA_BF16(d[2 * p],     ah[0], ah[1], ah[2], ah[3], bl[0], bl[1]);
                MMA_BF16(d[2 * p],     al[0], al[1], al[2], al[3], bh[0], bh[1]);
                MMA_BF16(d[2 * p + 1], ah[0], ah[1], ah[2], ah[3], bh[2], bh[3]);
                MMA_BF16(d[2 * p + 1], ah[0], ah[1], ah[2], ah[3], bl[2], bl[3]);
                MMA_BF16(d[2 * p + 1], al[0], al[1], al[2], al[3], bh[2], bh[3]);
            }
        }
        __syncthreads();
    }

    // epilogue: store bf16 features + fused fp32 attention logits
    int r0 = bm + warp * 16 + g;
    int r1 = r0 + 8;
    #pragma unroll
    for (int nt = 0; nt < NT; ++nt) {
        int c = nt * 8 + 2 * t;
        if (r0 < M) {
            __nv_bfloat162 p = __floats2bfloat162_rn(d[nt][0], d[nt][1]);
            *(__nv_bfloat162*)(Hb + (size_t)r0 * N + c) = p;
        }
        if (r1 < M) {
            __nv_bfloat162 p = __floats2bfloat162_rn(d[nt][2], d[nt][3]);
            *(__nv_bfloat162*)(Hb + (size_t)r1 * N + c) = p;
        }
    }
    float s1a = 0.f, s2a = 0.f, s1b = 0.f, s2b = 0.f;
    #pragma unroll
    for (int nt = 0; nt < NT; ++nt) {
        int c = nt * 8 + 2 * t;
        float w0 = asrc[c], w1 = asrc[c + 1];
        float u0 = adst[c], u1 = adst[c + 1];
        s1a += d[nt][0] * w0 + d[nt][1] * w1;
        s2a += d[nt][0] * u0 + d[nt][1] * u1;
        s1b += d[nt][2] * w0 + d[nt][3] * w1;
        s2b += d[nt][2] * u0 + d[nt][3] * u1;
    }
    #pragma unroll
    for (int o = 1; o <= 2; o <<= 1) {
        s1a += __shfl_xor_sync(0xffffffffu, s1a, o);
        s2a += __shfl_xor_sync(0xffffffffu, s2a, o);
        s1b += __shfl_xor_sync(0xffffffffu, s1b, o);
        s2b += __shfl_xor_sync(0xffffffffu, s2b, o);
    }
    if (t == 0) {
        if (r0 < M) { as_[r0] = s1a; ad_[r0] = s2a; }
        if (r1 < M) { as_[r1] = s1b; ad_[r1] = s2b; }
    }
}

// ---------------- fused segment-softmax + weighted aggregation (bf16 h) -----
// R11/R13 version: GW = C/8 lanes per edge (16B LDG.128 per lane); EPG = 32/GW
// edges per gather group, 2 batches in flight. fp32 accumulate.
template <int C, bool ACT>
__global__ void aggr_kernel(const int* __restrict__ off, const int* __restrict__ csr,
                            const __nv_bfloat16* __restrict__ hb,
                            const float* __restrict__ as_, const float* __restrict__ ad_,
                            const float* __restrict__ bias,
                            float* __restrict__ out, int nN) {
    const int GW  = C / 8;       // 8 for C=64, 4 for C=32
    const int EPG = 32 / GW;     // 4 or 8
    int warp = (blockIdx.x * blockDim.x + threadIdx.x) >> 5;
    int lane = threadIdx.x & 31;
    if (warp >= nN) return;
    int d   = warp;
    int j0  = off[d];
    int end = off[d + 1];
    float adv = ad_[d];
    int grp = lane / GW;
    int sub = lane % GW;
    float dlane = 0.f;
    float acc[8];
    #pragma unroll
    for (int i = 0; i < 8; ++i) acc[i] = 0.f;

    for (int base = j0; base < end; base += 32) {
        int nb = end - base;
        if (nb > 32) nb = 32;
        int s = csr[base + (lane < nb ? lane : 0)];
        float w = 0.f;
        if (lane < nb) {
            float e = as_[s] + adv;
            e = (e > 0.f) ? e : 0.2f * e;
            w = __expf(e);
            dlane += w;
        }
        for (int k = 0; k < nb; k += 2 * EPG) {
            int i0 = k + grp;
            int i1 = k + EPG + grp;
            int   s0 = __shfl_sync(0xffffffffu, s, i0 < nb ? i0 : 0);
            float w0 = __shfl_sync(0xffffffffu, w, i0 < nb ? i0 : 0);
            int   s1 = __shfl_sync(0xffffffffu, s, i1 < nb ? i1 : 0);
            float w1 = __shfl_sync(0xffffffffu, w, i1 < nb ? i1 : 0);
            if (i0 >= nb) w0 = 0.f;
            if (i1 >= nb) w1 = 0.f;
            uint4 q0 = *(const uint4*)(hb + (size_t)s0 * C + 8 * sub);
            {
                float2 f0 = __bfloat1622float2(*(__nv_bfloat162*)&q0.x);
                float2 f1 = __bfloat1622float2(*(__nv_bfloat162*)&q0.y);
                float2 f2 = __bfloat1622float2(*(__nv_bfloat162*)&q0.z);
                float2 f3 = __bfloat1622float2(*(__nv_bfloat162*)&q0.w);
                acc[0] += w0 * f0.x; acc[1] += w0 * f0.y;
                acc[2] += w0 * f1.x; acc[3] += w0 * f1.y;
                acc[4] += w0 * f2.x; acc[5] += w0 * f2.y;
                acc[6] += w0 * f3.x; acc[7] += w0 * f3.y;
            }
            if (i1 < nb || k + EPG < nb) {
                uint4 q1 = *(const uint4*)(hb + (size_t)s1 * C + 8 * sub);
                float2 f0 = __bfloat1622float2(*(__nv_bfloat162*)&q1.x);
                float2 f1 = __bfloat1622float2(*(__nv_bfloat162*)&q1.y);
                float2 f2 = __bfloat1622float2(*(__nv_bfloat162*)&q1.z);
                float2 f3 = __bfloat1622float2(*(__nv_bfloat162*)&q1.w);
                acc[0] += w1 * f0.x; acc[1] += w1 * f0.y;
                acc[2] += w1 * f1.x; acc[3] += w1 * f1.y;
                acc[4] += w1 * f2.x; acc[5] += w1 * f2.y;
                acc[6] += w1 * f3.x; acc[7] += w1 * f3.y;
            }
        }
    }

    #pragma unroll
    for (int o = GW; o < 32; o <<= 1) {
        #pragma unroll
        for (int i = 0; i < 8; ++i)
            acc[i] += __shfl_xor_sync(0xffffffffu, acc[i], o);
    }
    #pragma unroll
    for (int o = 16; o > 0; o >>= 1)
        dlane += __shfl_xor_sync(0xffffffffu, dlane, o);

    float inv = 1.f / (dlane + 1e-16f);
    if (lane < GW) {
        float4 b0 = *(const float4*)(bias + 8 * sub);
        float4 b1 = *(const float4*)(bias + 8 * sub + 4);
        float o0 = acc[0] * inv + b0.x;
        float o1 = acc[1] * inv + b0.y;
        float o2 = acc[2] * inv + b0.z;
        float o3 = acc[3] * inv + b0.w;
        float o4 = acc[4] * inv + b1.x;
        float o5 = acc[5] * inv + b1.y;
        float o6 = acc[6] * inv + b1.z;
        float o7 = acc[7] * inv + b1.w;
        if (ACT) {
            o0 = (o0 > 0.f) ? o0 : 0.01f * o0;
            o1 = (o1 > 0.f) ? o1 : 0.01f * o1;
            o2 = (o2 > 0.f) ? o2 : 0.01f * o2;
            o3 = (o3 > 0.f) ? o3 : 0.01f * o3;
            o4 = (o4 > 0.f) ? o4 : 0.01f * o4;
            o5 = (o5 > 0.f) ? o5 : 0.01f * o5;
            o6 = (o6 > 0.f) ? o6 : 0.01f * o6;
            o7 = (o7 > 0.f) ? o7 : 0.01f * o7;
        }
        *(float4*)(out + (size_t)d * C + 8 * sub)     = make_float4(o0, o1, o2, o3);
        *(float4*)(out + (size_t)d * C + 8 * sub + 4) = make_float4(o4, o5, o6, o7);
    }
}

// ---------------- launch ----------------------------------------------------
extern "C" void kernel_launch(void* const* d_in, const int* in_sizes, int n_in,
                              void* d_out, int out_size) {
    const float* x   = (const float*)d_in[0];
    const void*  ei  = d_in[1];
    const float* W1  = (const float*)d_in[2];
    const float* as1 = (const float*)d_in[3];
    const float* ad1 = (const float*)d_in[4];
    const float* b1  = (const float*)d_in[5];
    const float* W2  = (const float*)d_in[6];
    const float* as2 = (const float*)d_in[7];
    const float* ad2 = (const float*)d_in[8];
    const float* b2  = (const float*)d_in[9];
    const float* W3  = (const float*)d_in[10];
    const float* as3 = (const float*)d_in[11];
    const float* ad3 = (const float*)d_in[12];
    const float* b3  = (const float*)d_in[13];
    float* out = (float*)d_out;

    int E    = in_sizes[1] / 2;
    int nTot = E + N_NODES;

    __nv_bfloat16* hb;
    float *buf1, *buf2, *pas, *pad;
    int *deg, *off, *cur, *csr, *bsum;
    cudaGetSymbolAddress((void**)&hb,   g_hb);
    cudaGetSymbolAddress((void**)&buf1, g_buf1);
    cudaGetSymbolAddress((void**)&buf2, g_buf2);
    cudaGetSymbolAddress((void**)&pas,  g_as);
    cudaGetSymbolAddress((void**)&pad,  g_ad);
    cudaGetSymbolAddress((void**)&deg,  g_deg);
    cudaGetSymbolAddress((void**)&off,  g_off);
    cudaGetSymbolAddress((void**)&cur,  g_cur);
    cudaGetSymbolAddress((void**)&csr,  g_csr);
    cudaGetSymbolAddress((void**)&bsum, g_bsum);

    static cudaStream_t s1 = []() {
        cudaStream_t s; cudaStreamCreateWithFlags(&s, cudaStreamNonBlocking); return s;
    }();
    static cudaEvent_t evFork = []() {
        cudaEvent_t e; cudaEventCreateWithFlags(&e, cudaEventDisableTiming); return e;
    }();
    static cudaEvent_t evJoin = []() {
        cudaEvent_t e; cudaEventCreateWithFlags(&e, cudaEventDisableTiming); return e;
    }();
    static bool smemInit = []() {
        cudaFuncSetAttribute(gemm_tc_kernel<8>,
                             cudaFuncAttributeMaxDynamicSharedMemorySize, GEMM_DYN_SMEM);
        cudaFuncSetAttribute(gemm_tc_kernel<4>,
                             cudaFuncAttributeMaxDynamicSharedMemorySize, GEMM_DYN_SMEM);
        return true;
    }();
    (void)smemInit;

    int gemm_blocks = (N_NODES + 127) / 128;
    int node_warp_blocks = (N_NODES + 7) / 8;

    // ---- CSR prelude (launches 1-3) ----
    detect_kernel<<<1, 256>>>((const int*)ei, in_sizes[1]);
    zero_int_kernel<<<(N_NODES + 255) / 256, 256>>>(deg, N_NODES);
    hist_kernel<<<(nTot + 255) / 256, 256>>>(ei, deg, E, N_NODES);

    // ---- fork: GEMM1 (launch 4 -> ncu capture slot) on side stream ----
    cudaEventRecord(evFork, 0);
    cudaStreamWaitEvent(s1, evFork, 0);
    gemm_tc_kernel<8><<<gemm_blocks, 256, GEMM_DYN_SMEM, s1>>>(
        x, W1, hb, N_NODES, 256, 64, as1, ad1, pas, pad);

    // ---- rest of CSR build on default stream (overlapped with GEMM1) ----
    scanA_kernel<<<SCAN_NB, SCAN_B>>>(deg, off, bsum, N_NODES);
    scanB_kernel<<<1, 128>>>(bsum, SCAN_NB, off, N_NODES);
    scanC_kernel<<<SCAN_NB, SCAN_B>>>(off, cur, bsum, N_NODES);
    scatter_kernel<<<(nTot + 255) / 256, 256>>>(ei, cur, csr, E, N_NODES);

    cudaEventRecord(evJoin, s1);
    cudaStreamWaitEvent(0, evJoin, 0);

    // ---- layer 1 aggregation ----
    aggr_kernel<64, true><<<node_warp_blocks, 256>>>(off, csr, hb, pas, pad, b1, buf1, N_NODES);

    // ---- layer 2 ----
    gemm_tc_kernel<8><<<gemm_blocks, 256, GEMM_DYN_SMEM>>>(
        buf1, W2, hb, N_NODES, 64, 64, as2, ad2, pas, pad);
    aggr_kernel<64, true><<<node_warp_blocks, 256>>>(off, csr, hb, pas, pad, b2, buf2, N_NODES);

    // ---- layer 3 ----
    gemm_tc_kernel<4><<<gemm_blocks, 256, GEMM_DYN_SMEM>>>(
        buf2, W3, hb, N_NODES, 64, 32, as3, ad3, pas, pad);
    aggr_kernel<32, false><<<node_warp_blocks, 256>>>(off, csr, hb, pas, pad, b3, out, N_NODES);
}

// round 15
// speedup vs baseline: 1.0996x; 1.0996x over previous
#include <cuda_runtime.h>
#include <cuda_bf16.h>
#include <math.h>
#include <stdint.h>

#define N_NODES 100000
#define E_MAX   1750000
#define SCAN_B  1024
#define SCAN_NB ((N_NODES + SCAN_B - 1) / SCAN_B)   // 98

// ---------------- scratch (device globals; no allocation allowed) ----------
__device__ __nv_bfloat16 g_hb[N_NODES * 64];   // bf16 features (GEMM out / aggr in)
__device__ float g_buf1[N_NODES * 64];
__device__ float g_buf2[N_NODES * 64];
__device__ float g_as  [N_NODES];
__device__ float g_ad  [N_NODES];
__device__ int   g_deg [N_NODES];
__device__ int   g_off [N_NODES + 1];
__device__ int   g_cur [N_NODES];
__device__ int   g_csr [E_MAX];
__device__ int   g_bsum[128];
__device__ int   g_is32;

// ---------------- dtype detection (parallel) --------------------------------
__global__ void detect_kernel(const int* __restrict__ ei32, int nWords) {
    int lim = nWords < 65536 ? nWords : 65536;
    int any = 0;
    for (int i = 1 + 2 * threadIdx.x; i < lim; i += 2 * blockDim.x)
        any |= (ei32[i] != 0);
    any = __syncthreads_or(any);
    if (threadIdx.x == 0) g_is32 = any ? 1 : 0;
}

__device__ __forceinline__ int load_idx(const int* ei32, const long long* ei64,
                                        int is32, int i) {
    return is32 ? ei32[i] : (int)ei64[i];
}

// ---------------- CSR build --------------------------------------------------
__global__ void zero_int_kernel(int* p, int n) {
    int i = blockIdx.x * blockDim.x + threadIdx.x;
    if (i < n) p[i] = 0;
}

__global__ void hist_kernel(const void* __restrict__ ei, int* __restrict__ deg,
                            int nE, int nN) {
    int i = blockIdx.x * blockDim.x + threadIdx.x;
    int nTot = nE + nN;
    if (i >= nTot) return;
    int is32 = g_is32;
    const int* e32 = (const int*)ei;
    const long long* e64 = (const long long*)ei;
    int d = (i < nE) ? load_idx(e32, e64, is32, nE + i) : (i - nE);
    atomicAdd(&deg[d], 1);
}

__global__ void scanA_kernel(const int* __restrict__ deg, int* __restrict__ off,
                             int* __restrict__ bsum, int n) {
    __shared__ int sm[SCAN_B];
    int tid = threadIdx.x;
    int i = blockIdx.x * SCAN_B + tid;
    int v = (i < n) ? deg[i] : 0;
    sm[tid] = v;
    __syncthreads();
    #pragma unroll
    for (int s = 1; s < SCAN_B; s <<= 1) {
        int t = (tid >= s) ? sm[tid - s] : 0;
        __syncthreads();
        sm[tid] += t;
        __syncthreads();
    }
    if (i < n) off[i] = sm[tid] - v;
    if (tid == SCAN_B - 1) bsum[blockIdx.x] = sm[tid];
}

__global__ void scanB_kernel(int* __restrict__ bsum, int nb,
                             int* __restrict__ off, int n) {
    __shared__ int sm[128];
    int tid = threadIdx.x;
    int v = (tid < nb) ? bsum[tid] : 0;
    sm[tid] = v;
    __syncthreads();
    #pragma unroll
    for (int s = 1; s < 128; s <<= 1) {
        int t = (tid >= s) ? sm[tid - s] : 0;
        __syncthreads();
        sm[tid] += t;
        __syncthreads();
    }
    if (tid < nb) bsum[tid] = sm[tid] - v;
    if (tid == 127) off[n] = sm[127];
}

__global__ void scanC_kernel(int* __restrict__ off, int* __restrict__ cur,
                             const int* __restrict__ bsum, int n) {
    int i = blockIdx.x * SCAN_B + threadIdx.x;
    if (i >= n) return;
    int v = off[i] + bsum[blockIdx.x];
    off[i] = v;
    cur[i] = v;
}

__global__ void scatter_kernel(const void* __restrict__ ei,
                               int* __restrict__ cur, int* __restrict__ csr,
                               int nE, int nN) {
    int i = blockIdx.x * blockDim.x + threadIdx.x;
    int nTot = nE + nN;
    if (i >= nTot) return;
    int is32 = g_is32;
    const int* e32 = (const int*)ei;
    const long long* e64 = (const long long*)ei;
    int s, d;
    if (i < nE) {
        s = load_idx(e32, e64, is32, i);
        d = load_idx(e32, e64, is32, nE + i);
    } else {
        s = d = i - nE;
    }
    int pos = atomicAdd(&cur[d], 1);
    csr[pos] = s;
}

// ---------------- tensor-core GEMM (bf16x2-split, ldmatrix) + fused logits --
#define MMA_BF16(D, A0, A1, A2, A3, B0, B1)                                    \
    asm volatile(                                                              \
        "mma.sync.aligned.m16n8k16.row.col.f32.bf16.bf16.f32 "                 \
        "{%0,%1,%2,%3}, {%4,%5,%6,%7}, {%8,%9}, {%0,%1,%2,%3};\n"              \
        : "+f"(D[0]), "+f"(D[1]), "+f"(D[2]), "+f"(D[3])                       \
        : "r"(A0), "r"(A1), "r"(A2), "r"(A3), "r"(B0), "r"(B1))

#define LDSM4(R, ADDR)                                                         \
    asm volatile(                                                              \
        "ldmatrix.sync.aligned.m8n8.x4.shared.b16 {%0,%1,%2,%3}, [%4];\n"      \
        : "=r"(R[0]), "=r"(R[1]), "=r"(R[2]), "=r"(R[3]) : "r"(ADDR))

#define LDSM4T(R, ADDR)                                                        \
    asm volatile(                                                              \
        "ldmatrix.sync.aligned.m8n8.x4.trans.shared.b16 {%0,%1,%2,%3}, [%4];\n"\
        : "=r"(R[0]), "=r"(R[1]), "=r"(R[2]), "=r"(R[3]) : "r"(ADDR))

template <int NT>   // NT = N/8 (8 for N=64, 4 for N=32); NT even
__global__ __launch_bounds__(256, 2) void gemm_tc_kernel(
    const float* __restrict__ A, const float* __restrict__ B,
    __nv_bfloat16* __restrict__ Hb, int M, int K, int N,
    const float* __restrict__ asrc, const float* __restrict__ adst,
    float* __restrict__ as_, float* __restrict__ ad_) {
    const int BM = 128, BK = 32, STR = 40, BSTR = 72;
    __shared__ __nv_bfloat16 Ah[BM * STR], Al[BM * STR];
    __shared__ __nv_bfloat16 Bh[BK * BSTR], Bl[BK * BSTR];   // K-major [k][n]

    int tid  = threadIdx.x;
    int warp = tid >> 5;
    int lane = tid & 31;
    int g = lane >> 2;
    int t = lane & 3;
    int bm = blockIdx.x * BM;

    // A ldmatrix offsets (non-trans, [m][k] layout)
    int aRow = warp * 16 + (lane & 15);
    int aCol = (lane >> 4) * 8;
    uint32_t aOffH = (uint32_t)__cvta_generic_to_shared(Ah) + (aRow * STR + aCol) * 2;
    uint32_t aOffL = (uint32_t)__cvta_generic_to_shared(Al) + (aRow * STR + aCol) * 2;
    // B ldmatrix.trans offsets ([k][n] layout): lanes 0-15 -> k-rows 0-15 at
    // n-octet 0; lanes 16-31 -> k-rows 0-15 at n-octet 1.
    int bkRow = lane & 15;
    int bnOct = (lane >> 4) * 8;
    uint32_t bOffH = (uint32_t)__cvta_generic_to_shared(Bh) + (bkRow * BSTR + bnOct) * 2;
    uint32_t bOffL = (uint32_t)__cvta_generic_to_shared(Bl) + (bkRow * BSTR + bnOct) * 2;

    float d[NT][4];
    #pragma unroll
    for (int nt = 0; nt < NT; ++nt)
        #pragma unroll
        for (int r = 0; r < 4; ++r) d[nt][r] = 0.f;

    for (int k0 = 0; k0 < K; k0 += BK) {
        // ---- A tile 128x32 as hi/lo bf16 (direct load -> convert -> STS) ----
        #pragma unroll
        for (int it = 0; it < 8; ++it) {
            int idx2 = tid + it * 256;         // pair index, 2048 pairs
            int m  = idx2 >> 4;                // 16 pairs per row
            int kp = (idx2 & 15) * 2;
            int gm = bm + m;
            float2 v = make_float2(0.f, 0.f);
            if (gm < M) v = *(const float2*)(A + (size_t)gm * K + k0 + kp);
            __nv_bfloat16 h0 = __float2bfloat16(v.x);
            __nv_bfloat16 h1 = __float2bfloat16(v.y);
            __nv_bfloat162 ph; ph.x = h0; ph.y = h1;
            __nv_bfloat162 pl;
            pl.x = __float2bfloat16(v.x - __bfloat162float(h0));
            pl.y = __float2bfloat16(v.y - __bfloat162float(h1));
            *(__nv_bfloat162*)(Ah + m * STR + kp) = ph;
            *(__nv_bfloat162*)(Al + m * STR + kp) = pl;
        }
        // ---- B tile 32xN, K-major [k][n]: coalesced float2 loads, paired
        //      conflict-free STS.32 stores ----
        #pragma unroll
        for (int it = 0; it < 4; ++it) {
            int idx2 = tid + it * 256;         // 1024 pairs = 32k x 32 n-pairs
            int k  = idx2 >> 5;
            int np = (idx2 & 31) * 2;
            float2 v = make_float2(0.f, 0.f);
            if (np < N) v = *(const float2*)(B + (size_t)(k0 + k) * N + np);
            __nv_bfloat16 h0 = __float2bfloat16(v.x);
            __nv_bfloat16 h1 = __float2bfloat16(v.y);
            __nv_bfloat162 ph; ph.x = h0; ph.y = h1;
            __nv_bfloat162 pl;
            pl.x = __float2bfloat16(v.x - __bfloat162float(h0));
            pl.y = __float2bfloat16(v.y - __bfloat162float(h1));
            *(__nv_bfloat162*)(Bh + k * BSTR + np) = ph;
            *(__nv_bfloat162*)(Bl + k * BSTR + np) = pl;
        }
        __syncthreads();

        #pragma unroll
        for (int kk = 0; kk < BK; kk += 16) {
            unsigned int ah[4], al[4];
            LDSM4(ah, aOffH + kk * 2);
            LDSM4(al, aOffL + kk * 2);
            #pragma unroll
            for (int p = 0; p < NT / 2; ++p) {
                unsigned int bh[4], bl[4];
                LDSM4T(bh, bOffH + (kk * BSTR + p * 16) * 2);
                LDSM4T(bl, bOffL + (kk * BSTR + p * 16) * 2);
                MMA_BF16(d[2 * p],     ah[0], ah[1], ah[2], ah[3], bh[0], bh[1]);
                MMA_BF16(d[2 * p],     ah[0], ah[1], ah[2], ah[3], bl[0], bl[1]);
                MMA_BF16(d[2 * p],     al[0], al[1], al[2], al[3], bh[0], bh[1]);
                MMA_BF16(d[2 * p + 1], ah[0], ah[1], ah[2], ah[3], bh[2], bh[3]);
                MMA_BF16(d[2 * p + 1], ah[0], ah[1], ah[2], ah[3], bl[2], bl[3]);
                MMA_BF16(d[2 * p + 1], al[0], al[1], al[2], al[3], bh[2], bh[3]);
            }
        }
        __syncthreads();
    }

    // epilogue: store bf16 features + fused fp32 attention logits
    int r0 = bm + warp * 16 + g;
    int r1 = r0 + 8;
    #pragma unroll
    for (int nt = 0; nt < NT; ++nt) {
        int c = nt * 8 + 2 * t;
        if (r0 < M) {
            __nv_bfloat162 p = __floats2bfloat162_rn(d[nt][0], d[nt][1]);
            *(__nv_bfloat162*)(Hb + (size_t)r0 * N + c) = p;
        }
        if (r1 < M) {
            __nv_bfloat162 p = __floats2bfloat162_rn(d[nt][2], d[nt][3]);
            *(__nv_bfloat162*)(Hb + (size_t)r1 * N + c) = p;
        }
    }
    float s1a = 0.f, s2a = 0.f, s1b = 0.f, s2b = 0.f;
    #pragma unroll
    for (int nt = 0; nt < NT; ++nt) {
        int c = nt * 8 + 2 * t;
        float w0 = asrc[c], w1 = asrc[c + 1];
        float u0 = adst[c], u1 = adst[c + 1];
        s1a += d[nt][0] * w0 + d[nt][1] * w1;
        s2a += d[nt][0] * u0 + d[nt][1] * u1;
        s1b += d[nt][2] * w0 + d[nt][3] * w1;
        s2b += d[nt][2] * u0 + d[nt][3] * u1;
    }
    #pragma unroll
    for (int o = 1; o <= 2; o <<= 1) {
        s1a += __shfl_xor_sync(0xffffffffu, s1a, o);
        s2a += __shfl_xor_sync(0xffffffffu, s2a, o);
        s1b += __shfl_xor_sync(0xffffffffu, s1b, o);
        s2b += __shfl_xor_sync(0xffffffffu, s2b, o);
    }
    if (t == 0) {
        if (r0 < M) { as_[r0] = s1a; ad_[r0] = s2a; }
        if (r1 < M) { as_[r1] = s1b; ad_[r1] = s2b; }
    }
}

// ---------------- fused segment-softmax + weighted aggregation (bf16 h) -----
// R13 version: GW = C/8 lanes per edge (16B LDG.128 per lane); EPG = 32/GW
// edges per gather group, 2 batches in flight. fp32 accumulate.
template <int C, bool ACT>
__global__ void aggr_kernel(const int* __restrict__ off, const int* __restrict__ csr,
                            const __nv_bfloat16* __restrict__ hb,
                            const float* __restrict__ as_, const float* __restrict__ ad_,
                            const float* __restrict__ bias,
                            float* __restrict__ out, int nN) {
    const int GW  = C / 8;       // 8 for C=64, 4 for C=32
    const int EPG = 32 / GW;     // 4 or 8
    int warp = (blockIdx.x * blockDim.x + threadIdx.x) >> 5;
    int lane = threadIdx.x & 31;
    if (warp >= nN) return;
    int d   = warp;
    int j0  = off[d];
    int end = off[d + 1];
    float adv = ad_[d];
    int grp = lane / GW;
    int sub = lane % GW;
    float dlane = 0.f;
    float acc[8];
    #pragma unroll
    for (int i = 0; i < 8; ++i) acc[i] = 0.f;

    for (int base = j0; base < end; base += 32) {
        int nb = end - base;
        if (nb > 32) nb = 32;
        int s = csr[base + (lane < nb ? lane : 0)];
        float w = 0.f;
        if (lane < nb) {
            float e = as_[s] + adv;
            e = (e > 0.f) ? e : 0.2f * e;
            w = __expf(e);
            dlane += w;
        }
        for (int k = 0; k < nb; k += 2 * EPG) {
            int i0 = k + grp;
            int i1 = k + EPG + grp;
            int   s0 = __shfl_sync(0xffffffffu, s, i0 < nb ? i0 : 0);
            float w0 = __shfl_sync(0xffffffffu, w, i0 < nb ? i0 : 0);
            int   s1 = __shfl_sync(0xffffffffu, s, i1 < nb ? i1 : 0);
            float w1 = __shfl_sync(0xffffffffu, w, i1 < nb ? i1 : 0);
            if (i0 >= nb) w0 = 0.f;
            if (i1 >= nb) w1 = 0.f;
            uint4 q0 = *(const uint4*)(hb + (size_t)s0 * C + 8 * sub);
            {
                float2 f0 = __bfloat1622float2(*(__nv_bfloat162*)&q0.x);
                float2 f1 = __bfloat1622float2(*(__nv_bfloat162*)&q0.y);
                float2 f2 = __bfloat1622float2(*(__nv_bfloat162*)&q0.z);
                float2 f3 = __bfloat1622float2(*(__nv_bfloat162*)&q0.w);
                acc[0] += w0 * f0.x; acc[1] += w0 * f0.y;
                acc[2] += w0 * f1.x; acc[3] += w0 * f1.y;
                acc[4] += w0 * f2.x; acc[5] += w0 * f2.y;
                acc[6] += w0 * f3.x; acc[7] += w0 * f3.y;
            }
            if (i1 < nb || k + EPG < nb) {
                uint4 q1 = *(const uint4*)(hb + (size_t)s1 * C + 8 * sub);
                float2 f0 = __bfloat1622float2(*(__nv_bfloat162*)&q1.x);
                float2 f1 = __bfloat1622float2(*(__nv_bfloat162*)&q1.y);
                float2 f2 = __bfloat1622float2(*(__nv_bfloat162*)&q1.z);
                float2 f3 = __bfloat1622float2(*(__nv_bfloat162*)&q1.w);
                acc[0] += w1 * f0.x; acc[1] += w1 * f0.y;
                acc[2] += w1 * f1.x; acc[3] += w1 * f1.y;
                acc[4] += w1 * f2.x; acc[5] += w1 * f2.y;
                acc[6] += w1 * f3.x; acc[7] += w1 * f3.y;
            }
        }
    }

    #pragma unroll
    for (int o = GW; o < 32; o <<= 1) {
        #pragma unroll
        for (int i = 0; i < 8; ++i)
            acc[i] += __shfl_xor_sync(0xffffffffu, acc[i], o);
    }
    #pragma unroll
    for (int o = 16; o > 0; o >>= 1)
        dlane += __shfl_xor_sync(0xffffffffu, dlane, o);

    float inv = 1.f / (dlane + 1e-16f);
    if (lane < GW) {
        float4 b0 = *(const float4*)(bias + 8 * sub);
        float4 b1 = *(const float4*)(bias + 8 * sub + 4);
        float o0 = acc[0] * inv + b0.x;
        float o1 = acc[1] * inv + b0.y;
        float o2 = acc[2] * inv + b0.z;
        float o3 = acc[3] * inv + b0.w;
        float o4 = acc[4] * inv + b1.x;
        float o5 = acc[5] * inv + b1.y;
        float o6 = acc[6] * inv + b1.z;
        float o7 = acc[7] * inv + b1.w;
        if (ACT) {
            o0 = (o0 > 0.f) ? o0 : 0.01f * o0;
            o1 = (o1 > 0.f) ? o1 : 0.01f * o1;
            o2 = (o2 > 0.f) ? o2 : 0.01f * o2;
            o3 = (o3 > 0.f) ? o3 : 0.01f * o3;
            o4 = (o4 > 0.f) ? o4 : 0.01f * o4;
            o5 = (o5 > 0.f) ? o5 : 0.01f * o5;
            o6 = (o6 > 0.f) ? o6 : 0.01f * o6;
            o7 = (o7 > 0.f) ? o7 : 0.01f * o7;
        }
        *(float4*)(out + (size_t)d * C + 8 * sub)     = make_float4(o0, o1, o2, o3);
        *(float4*)(out + (size_t)d * C + 8 * sub + 4) = make_float4(o4, o5, o6, o7);
    }
}

// ---------------- launch ----------------------------------------------------
extern "C" void kernel_launch(void* const* d_in, const int* in_sizes, int n_in,
                              void* d_out, int out_size) {
    const float* x   = (const float*)d_in[0];
    const void*  ei  = d_in[1];
    const float* W1  = (const float*)d_in[2];
    const float* as1 = (const float*)d_in[3];
    const float* ad1 = (const float*)d_in[4];
    const float* b1  = (const float*)d_in[5];
    const float* W2  = (const float*)d_in[6];
    const float* as2 = (const float*)d_in[7];
    const float* ad2 = (const float*)d_in[8];
    const float* b2  = (const float*)d_in[9];
    const float* W3  = (const float*)d_in[10];
    const float* as3 = (const float*)d_in[11];
    const float* ad3 = (const float*)d_in[12];
    const float* b3  = (const float*)d_in[13];
    float* out = (float*)d_out;

    int E    = in_sizes[1] / 2;
    int nTot = E + N_NODES;

    __nv_bfloat16* hb;
    float *buf1, *buf2, *pas, *pad;
    int *deg, *off, *cur, *csr, *bsum;
    cudaGetSymbolAddress((void**)&hb,   g_hb);
    cudaGetSymbolAddress((void**)&buf1, g_buf1);
    cudaGetSymbolAddress((void**)&buf2, g_buf2);
    cudaGetSymbolAddress((void**)&pas,  g_as);
    cudaGetSymbolAddress((void**)&pad,  g_ad);
    cudaGetSymbolAddress((void**)&deg,  g_deg);
    cudaGetSymbolAddress((void**)&off,  g_off);
    cudaGetSymbolAddress((void**)&cur,  g_cur);
    cudaGetSymbolAddress((void**)&csr,  g_csr);
    cudaGetSymbolAddress((void**)&bsum, g_bsum);

    static cudaStream_t s1 = []() {
        cudaStream_t s; cudaStreamCreateWithFlags(&s, cudaStreamNonBlocking); return s;
    }();
    static cudaEvent_t evFork = []() {
        cudaEvent_t e; cudaEventCreateWithFlags(&e, cudaEventDisableTiming); return e;
    }();
    static cudaEvent_t evJoin = []() {
        cudaEvent_t e; cudaEventCreateWithFlags(&e, cudaEventDisableTiming); return e;
    }();

    int gemm_blocks = (N_NODES + 127) / 128;
    int node_warp_blocks = (N_NODES + 7) / 8;

    // ---- CSR prelude (launches 1-3) ----
    detect_kernel<<<1, 256>>>((const int*)ei, in_sizes[1]);
    zero_int_kernel<<<(N_NODES + 255) / 256, 256>>>(deg, N_NODES);
    hist_kernel<<<(nTot + 255) / 256, 256>>>(ei, deg, E, N_NODES);

    // ---- fork: GEMM1 (launch 4 -> ncu capture slot) on side stream ----
    cudaEventRecord(evFork, 0);
    cudaStreamWaitEvent(s1, evFork, 0);
    gemm_tc_kernel<8><<<gemm_blocks, 256, 0, s1>>>(x, W1, hb, N_NODES, 256, 64,
                                                   as1, ad1, pas, pad);

    // ---- rest of CSR build on default stream (overlapped with GEMM1) ----
    scanA_kernel<<<SCAN_NB, SCAN_B>>>(deg, off, bsum, N_NODES);
    scanB_kernel<<<1, 128>>>(bsum, SCAN_NB, off, N_NODES);
    scanC_kernel<<<SCAN_NB, SCAN_B>>>(off, cur, bsum, N_NODES);
    scatter_kernel<<<(nTot + 255) / 256, 256>>>(ei, cur, csr, E, N_NODES);

    cudaEventRecord(evJoin, s1);
    cudaStreamWaitEvent(0, evJoin, 0);

    // ---- layer 1 aggregation ----
    aggr_kernel<64, true><<<node_warp_blocks, 256>>>(off, csr, hb, pas, pad, b1, buf1, N_NODES);

    // ---- layer 2 ----
    gemm_tc_kernel<8><<<gemm_blocks, 256>>>(buf1, W2, hb, N_NODES, 64, 64, as2, ad2, pas, pad);
    aggr_kernel<64, true><<<node_warp_blocks, 256>>>(off, csr, hb, pas, pad, b2, buf2, N_NODES);

    // ---- layer 3 ----
    gemm_tc_kernel<4><<<gemm_blocks, 256>>>(buf2, W3, hb, N_NODES, 64, 32, as3, ad3, pas, pad);
    aggr_kernel<32, false><<<node_warp_blocks, 256>>>(off, csr, hb, pas, pad, b3, out, N_NODES);
}